// round 3
// baseline (speedup 1.0000x reference)
#include <cuda_runtime.h>

// Scratch (device globals — no runtime allocation allowed)
__device__ float g_part   [4 * 64 * 1024];  // partial column sums of v (64 chunks of 16 rows)
__device__ float g_rowpart[8 * 4 * 1024];   // split-K partials of vsum @ Wv
__device__ float g_wosum  [64 * 1024];      // WoSum[d][m] = sum_j Wo[j*64+d][m]
__device__ float g_outrows[64 * 1024];      // 16 distinct out rows per batch

// ---------------------------------------------------------------------------
// K1: partial column sums of v. Block (s,b) handles 16 rows; thread owns one
// float4 column group. part[b][s][c] = sum_{l in 16-row chunk} v[b][l][c]
// ---------------------------------------------------------------------------
__global__ __launch_bounds__(256) void colsum_kernel(const float* __restrict__ v,
                                                     float* __restrict__ part) {
    const int s = blockIdx.x, b = blockIdx.y, t = threadIdx.x;
    const float4* p = (const float4*)(v + ((size_t)(b * 1024 + s * 16)) * 1024) + t;
    float4 a0 = make_float4(0.f, 0.f, 0.f, 0.f);
    float4 a1 = make_float4(0.f, 0.f, 0.f, 0.f);
#pragma unroll
    for (int i = 0; i < 16; i += 2) {
        float4 x = p[(size_t)i * 256];
        float4 y = p[(size_t)(i + 1) * 256];
        a0.x += x.x; a0.y += x.y; a0.z += x.z; a0.w += x.w;
        a1.x += y.x; a1.y += y.y; a1.z += y.z; a1.w += y.w;
    }
    float4 r = make_float4(a0.x + a1.x, a0.y + a1.y, a0.z + a1.z, a0.w + a1.w);
    ((float4*)(part + (size_t)(b * 64 + s) * 1024))[t] = r;
}

// ---------------------------------------------------------------------------
// K2: split-K of rowsum[b][o] = sum_k vsum[b][k] * Wv[k][o].
// Block (oc, kc): reduce part -> vs for its 128-k chunk, then partial GEMM.
// Writes rowpart[kc][b][o] (no atomics, no zero kernel).
// ---------------------------------------------------------------------------
__global__ __launch_bounds__(256) void vwv_kernel(const float* __restrict__ part,
                                                  const float* __restrict__ Wv,
                                                  float* __restrict__ rowpart) {
    __shared__ float vs[4][128];
    const int oc = blockIdx.x, kc = blockIdx.y, t = threadIdx.x;
    for (int idx = t; idx < 512; idx += 256) {
        int b = idx >> 7, kk = idx & 127;
        int k = kc * 128 + kk;
        float a0 = 0.f, a1 = 0.f;
#pragma unroll
        for (int s = 0; s < 64; s += 2) {
            a0 += part[(size_t)(b * 64 + s) * 1024 + k];
            a1 += part[(size_t)(b * 64 + s + 1) * 1024 + k];
        }
        vs[b][kk] = a0 + a1;
    }
    __syncthreads();
    const int o = oc * 256 + t;
    float a0 = 0.f, a1 = 0.f, a2 = 0.f, a3 = 0.f;
#pragma unroll 8
    for (int kk = 0; kk < 128; ++kk) {
        float w = Wv[(size_t)(kc * 128 + kk) * 1024 + o];
        a0 = fmaf(vs[0][kk], w, a0);
        a1 = fmaf(vs[1][kk], w, a1);
        a2 = fmaf(vs[2][kk], w, a2);
        a3 = fmaf(vs[3][kk], w, a3);
    }
    float* rp = rowpart + (size_t)kc * 4096;
    rp[0 * 1024 + o] = a0;
    rp[1 * 1024 + o] = a1;
    rp[2 * 1024 + o] = a2;
    rp[3 * 1024 + o] = a3;
}

// ---------------------------------------------------------------------------
// K3: WoSum[d][m4] = sum_{j<16} Wo[(j*64+d)][m4], float4 with explicit MLP.
// 64 blocks x 256 threads = 16384 threads, one float4 output each.
// ---------------------------------------------------------------------------
__global__ __launch_bounds__(256) void wosum_kernel(const float* __restrict__ Wo,
                                                    float* __restrict__ wosum) {
    const int d  = blockIdx.x;          // 0..63
    const int t  = threadIdx.x;         // float4 index within the 1024-row
    const float4* src = (const float4*)(Wo + (size_t)d * 1024) + t;
    float4 a0 = make_float4(0.f, 0.f, 0.f, 0.f);
    float4 a1 = make_float4(0.f, 0.f, 0.f, 0.f);
    float4 a2 = make_float4(0.f, 0.f, 0.f, 0.f);
    float4 a3 = make_float4(0.f, 0.f, 0.f, 0.f);
#pragma unroll
    for (int j = 0; j < 16; j += 4) {
        float4 x0 = src[(size_t)(j + 0) * 64 * 256];
        float4 x1 = src[(size_t)(j + 1) * 64 * 256];
        float4 x2 = src[(size_t)(j + 2) * 64 * 256];
        float4 x3 = src[(size_t)(j + 3) * 64 * 256];
        a0.x += x0.x; a0.y += x0.y; a0.z += x0.z; a0.w += x0.w;
        a1.x += x1.x; a1.y += x1.y; a1.z += x1.z; a1.w += x1.w;
        a2.x += x2.x; a2.y += x2.y; a2.z += x2.z; a2.w += x2.w;
        a3.x += x3.x; a3.y += x3.y; a3.z += x3.z; a3.w += x3.w;
    }
    float4 r = make_float4(a0.x + a1.x + a2.x + a3.x,
                           a0.y + a1.y + a2.y + a3.y,
                           a0.z + a1.z + a2.z + a3.z,
                           a0.w + a1.w + a2.w + a3.w);
    ((float4*)(wosum + (size_t)d * 1024))[t] = r;
}

// ---------------------------------------------------------------------------
// K4: outrows[bn][m] = sum_d rs[bn][d] * WoSum[d][m];
// rs[bn][d] = sum_{kc<8} rowpart[kc][b][n*64+d]
// ---------------------------------------------------------------------------
__global__ __launch_bounds__(256) void outrows_kernel(const float* __restrict__ rowpart,
                                                      const float* __restrict__ wosum,
                                                      float* __restrict__ outrows) {
    __shared__ float rs[64];
    const int mc = blockIdx.x, bn = blockIdx.y, t = threadIdx.x;
    if (t < 64) {
        const int b = bn >> 4, o = (bn & 15) * 64 + t;
        float a = 0.f;
#pragma unroll
        for (int kc = 0; kc < 8; ++kc)
            a += rowpart[(size_t)(kc * 4 + b) * 1024 + o];
        rs[t] = a;
    }
    __syncthreads();
    const int m = mc * 256 + t;
    float a = 0.f;
#pragma unroll
    for (int d = 0; d < 64; ++d) a = fmaf(rs[d], wosum[d * 1024 + m], a);
    outrows[bn * 1024 + m] = a;
}

// ---------------------------------------------------------------------------
// K5: residual add + LayerNorm. Row (b,l) uses outrows[b*16 + l/64].
// ---------------------------------------------------------------------------
__global__ __launch_bounds__(256) void ln_kernel(const float* __restrict__ outrows,
                                                 const float* __restrict__ q,
                                                 const float* __restrict__ gamma,
                                                 const float* __restrict__ beta,
                                                 float* __restrict__ out) {
    __shared__ float wsum[8], wsq[8], stat[2];
    const int row = blockIdx.x;
    const int tid = threadIdx.x;
    const int bn = (row >> 10) * 16 + ((row & 1023) >> 6);

    float4 y = ((const float4*)(outrows + (size_t)bn * 1024))[tid];
    float4 r = ((const float4*)(q + (size_t)row * 1024))[tid];
    float x0 = y.x + r.x, x1 = y.y + r.y, x2 = y.z + r.z, x3 = y.w + r.w;

    float s  = x0 + x1 + x2 + x3;
    float sq = x0 * x0 + x1 * x1 + x2 * x2 + x3 * x3;
#pragma unroll
    for (int off = 16; off >= 1; off >>= 1) {
        s  += __shfl_xor_sync(0xffffffffu, s,  off);
        sq += __shfl_xor_sync(0xffffffffu, sq, off);
    }
    if ((tid & 31) == 0) { wsum[tid >> 5] = s; wsq[tid >> 5] = sq; }
    __syncthreads();
    if (tid == 0) {
        float S = 0.f, Qm = 0.f;
#pragma unroll
        for (int w = 0; w < 8; ++w) { S += wsum[w]; Qm += wsq[w]; }
        float mean = S * (1.f / 1024.f);
        float var  = Qm * (1.f / 1024.f) - mean * mean;
        stat[0] = mean;
        stat[1] = rsqrtf(var + 1e-6f);
    }
    __syncthreads();
    float mean = stat[0], inv = stat[1];
    float4 g  = ((const float4*)gamma)[tid];
    float4 bt = ((const float4*)beta)[tid];
    float4 o4 = make_float4((x0 - mean) * inv * g.x + bt.x,
                            (x1 - mean) * inv * g.y + bt.y,
                            (x2 - mean) * inv * g.z + bt.z,
                            (x3 - mean) * inv * g.w + bt.w);
    ((float4*)(out + (size_t)row * 1024))[tid] = o4;
}

// ---------------------------------------------------------------------------
extern "C" void kernel_launch(void* const* d_in, const int* in_sizes, int n_in,
                              void* d_out, int out_size) {
    (void)in_sizes; (void)n_in; (void)out_size;
    const float* q     = (const float*)d_in[0];
    const float* v     = (const float*)d_in[2];
    const float* Wv    = (const float*)d_in[6];
    const float* Wo    = (const float*)d_in[7];
    const float* gamma = (const float*)d_in[8];
    const float* beta  = (const float*)d_in[9];
    float* out = (float*)d_out;

    float *part, *rowpart, *wosum, *outrows;
    cudaGetSymbolAddress((void**)&part,    g_part);
    cudaGetSymbolAddress((void**)&rowpart, g_rowpart);
    cudaGetSymbolAddress((void**)&wosum,   g_wosum);
    cudaGetSymbolAddress((void**)&outrows, g_outrows);

    wosum_kernel  <<<64, 256>>>(Wo, wosum);
    colsum_kernel <<<dim3(64, 4), 256>>>(v, part);
    vwv_kernel    <<<dim3(4, 8), 256>>>(part, Wv, rowpart);
    outrows_kernel<<<dim3(4, 64), 256>>>(rowpart, wosum, outrows);
    ln_kernel     <<<4096, 256>>>(outrows, q, gamma, beta, out);
}

// round 4
// speedup vs baseline: 1.0520x; 1.0520x over previous
#include <cuda_runtime.h>

// Scratch (device globals — no runtime allocation allowed)
__device__ float g_part   [4 * 64 * 1024];  // partial column sums of v (64 chunks of 16 rows)
__device__ float g_rowpart[8 * 4 * 1024];   // split-K partials of vsum @ Wv
__device__ float g_wosum  [64 * 1024];      // WoSum[d][m] = sum_j Wo[j*64+d][m]
__device__ float g_outrows[64 * 1024];      // 16 distinct out rows per batch

// ---------------------------------------------------------------------------
// L1 (fused): blocks 0..255 -> colsum of v; blocks 256..319 -> wosum of Wo.
// colsum: part[b][s][c] = sum over 16-row chunk of v[b][l][c]
// wosum : wosum[d][m]   = sum_{j<16} Wo[j*64+d][m]
// ---------------------------------------------------------------------------
__global__ __launch_bounds__(256) void prep_kernel(const float* __restrict__ v,
                                                   const float* __restrict__ Wo,
                                                   float* __restrict__ part,
                                                   float* __restrict__ wosum) {
    const int t = threadIdx.x;
    if (blockIdx.x < 256) {
        const int s = blockIdx.x >> 2, b = blockIdx.x & 3;
        const float4* p = (const float4*)(v + ((size_t)(b * 1024 + s * 16)) * 1024) + t;
        float4 a0 = make_float4(0.f, 0.f, 0.f, 0.f);
        float4 a1 = make_float4(0.f, 0.f, 0.f, 0.f);
#pragma unroll
        for (int i = 0; i < 16; i += 2) {
            float4 x = p[(size_t)i * 256];
            float4 y = p[(size_t)(i + 1) * 256];
            a0.x += x.x; a0.y += x.y; a0.z += x.z; a0.w += x.w;
            a1.x += y.x; a1.y += y.y; a1.z += y.z; a1.w += y.w;
        }
        float4 r = make_float4(a0.x + a1.x, a0.y + a1.y, a0.z + a1.z, a0.w + a1.w);
        ((float4*)(part + (size_t)(b * 64 + s) * 1024))[t] = r;
    } else {
        const int d = blockIdx.x - 256;      // 0..63
        const float4* src = (const float4*)(Wo + (size_t)d * 1024) + t;
        float4 a0 = make_float4(0.f, 0.f, 0.f, 0.f);
        float4 a1 = make_float4(0.f, 0.f, 0.f, 0.f);
        float4 a2 = make_float4(0.f, 0.f, 0.f, 0.f);
        float4 a3 = make_float4(0.f, 0.f, 0.f, 0.f);
#pragma unroll
        for (int j = 0; j < 16; j += 4) {
            float4 x0 = src[(size_t)(j + 0) * 64 * 256];
            float4 x1 = src[(size_t)(j + 1) * 64 * 256];
            float4 x2 = src[(size_t)(j + 2) * 64 * 256];
            float4 x3 = src[(size_t)(j + 3) * 64 * 256];
            a0.x += x0.x; a0.y += x0.y; a0.z += x0.z; a0.w += x0.w;
            a1.x += x1.x; a1.y += x1.y; a1.z += x1.z; a1.w += x1.w;
            a2.x += x2.x; a2.y += x2.y; a2.z += x2.z; a2.w += x2.w;
            a3.x += x3.x; a3.y += x3.y; a3.z += x3.z; a3.w += x3.w;
        }
        float4 r = make_float4(a0.x + a1.x + a2.x + a3.x,
                               a0.y + a1.y + a2.y + a3.y,
                               a0.z + a1.z + a2.z + a3.z,
                               a0.w + a1.w + a2.w + a3.w);
        ((float4*)(wosum + (size_t)d * 1024))[t] = r;
    }
}

// ---------------------------------------------------------------------------
// L2: split-K of rowsum[b][o] = sum_k vsum[b][k] * Wv[k][o].
// Block (oc, kc): reduce part -> vs for its 128-k chunk, then partial GEMM.
// ---------------------------------------------------------------------------
__global__ __launch_bounds__(256) void vwv_kernel(const float* __restrict__ part,
                                                  const float* __restrict__ Wv,
                                                  float* __restrict__ rowpart) {
    __shared__ float vs[4][128];
    const int oc = blockIdx.x, kc = blockIdx.y, t = threadIdx.x;
    for (int idx = t; idx < 512; idx += 256) {
        int b = idx >> 7, kk = idx & 127;
        int k = kc * 128 + kk;
        float a0 = 0.f, a1 = 0.f;
#pragma unroll
        for (int s = 0; s < 64; s += 2) {
            a0 += part[(size_t)(b * 64 + s) * 1024 + k];
            a1 += part[(size_t)(b * 64 + s + 1) * 1024 + k];
        }
        vs[b][kk] = a0 + a1;
    }
    __syncthreads();
    const int o = oc * 256 + t;
    float a0 = 0.f, a1 = 0.f, a2 = 0.f, a3 = 0.f;
#pragma unroll 8
    for (int kk = 0; kk < 128; ++kk) {
        float w = Wv[(size_t)(kc * 128 + kk) * 1024 + o];
        a0 = fmaf(vs[0][kk], w, a0);
        a1 = fmaf(vs[1][kk], w, a1);
        a2 = fmaf(vs[2][kk], w, a2);
        a3 = fmaf(vs[3][kk], w, a3);
    }
    float* rp = rowpart + (size_t)kc * 4096;
    rp[0 * 1024 + o] = a0;
    rp[1 * 1024 + o] = a1;
    rp[2 * 1024 + o] = a2;
    rp[3 * 1024 + o] = a3;
}

// ---------------------------------------------------------------------------
// L3: outrows = rs @ wosum   ([64,64] @ [64,1024]) with smem staging.
// Grid (8 mc, 8 bng). Block: stages ws[64][128] (32KB) + rs[8][64],
// computes 8 bn x 128 m outputs (thread = 1 bn x 1 float4-of-m).
// rs[bn][d] = sum_{kc<8} rowpart[kc][b][n*64+d]  (split-K fold, free here)
// ---------------------------------------------------------------------------
__global__ __launch_bounds__(256) void outrows_kernel(const float* __restrict__ rowpart,
                                                      const float* __restrict__ wosum,
                                                      float* __restrict__ outrows) {
    __shared__ float4 ws[64][32];   // [d][m4] : 64 x 128 floats = 32 KB
    __shared__ float  rs[8][64];
    const int mc = blockIdx.x, bng = blockIdx.y, t = threadIdx.x;

    // stage wosum tile: 2048 float4, 8 per thread, coalesced
#pragma unroll
    for (int it = 0; it < 8; ++it) {
        int idx = t + it * 256;            // 0..2047
        int d = idx >> 5, m4 = idx & 31;
        ws[d][m4] = *((const float4*)(wosum + (size_t)d * 1024 + mc * 128) + m4);
    }
    // stage rs: 512 entries, 2 per thread, each folds 8 split-K partials
#pragma unroll
    for (int it = 0; it < 2; ++it) {
        int idx = t + it * 256;            // 0..511
        int bnl = idx >> 6, d = idx & 63;
        int bn = bng * 8 + bnl;
        int b = bn >> 4, o = (bn & 15) * 64 + d;
        float a = 0.f;
#pragma unroll
        for (int kc = 0; kc < 8; ++kc)
            a += rowpart[(size_t)(kc * 4 + b) * 1024 + o];
        rs[bnl][d] = a;
    }
    __syncthreads();

    const int bnl = t >> 5, m4 = t & 31;   // warp = bnl -> rs broadcast
    float4 acc = make_float4(0.f, 0.f, 0.f, 0.f);
#pragma unroll
    for (int d = 0; d < 64; ++d) {
        float a = rs[bnl][d];
        float4 w = ws[d][m4];
        acc.x = fmaf(a, w.x, acc.x);
        acc.y = fmaf(a, w.y, acc.y);
        acc.z = fmaf(a, w.z, acc.z);
        acc.w = fmaf(a, w.w, acc.w);
    }
    const int bn = bng * 8 + bnl;
    *((float4*)(outrows + (size_t)bn * 1024 + mc * 128) + m4) = acc;
}

// ---------------------------------------------------------------------------
// L4: residual add + LayerNorm. Row (b,l) uses outrows[b*16 + l/64].
// ---------------------------------------------------------------------------
__global__ __launch_bounds__(256) void ln_kernel(const float* __restrict__ outrows,
                                                 const float* __restrict__ q,
                                                 const float* __restrict__ gamma,
                                                 const float* __restrict__ beta,
                                                 float* __restrict__ out) {
    __shared__ float wsum[8], wsq[8], stat[2];
    const int row = blockIdx.x;
    const int tid = threadIdx.x;
    const int bn = (row >> 10) * 16 + ((row & 1023) >> 6);

    float4 y = ((const float4*)(outrows + (size_t)bn * 1024))[tid];
    float4 r = ((const float4*)(q + (size_t)row * 1024))[tid];
    float x0 = y.x + r.x, x1 = y.y + r.y, x2 = y.z + r.z, x3 = y.w + r.w;

    float s  = x0 + x1 + x2 + x3;
    float sq = x0 * x0 + x1 * x1 + x2 * x2 + x3 * x3;
#pragma unroll
    for (int off = 16; off >= 1; off >>= 1) {
        s  += __shfl_xor_sync(0xffffffffu, s,  off);
        sq += __shfl_xor_sync(0xffffffffu, sq, off);
    }
    if ((tid & 31) == 0) { wsum[tid >> 5] = s; wsq[tid >> 5] = sq; }
    __syncthreads();
    if (tid == 0) {
        float S = 0.f, Qm = 0.f;
#pragma unroll
        for (int w = 0; w < 8; ++w) { S += wsum[w]; Qm += wsq[w]; }
        float mean = S * (1.f / 1024.f);
        float var  = Qm * (1.f / 1024.f) - mean * mean;
        stat[0] = mean;
        stat[1] = rsqrtf(var + 1e-6f);
    }
    __syncthreads();
    float mean = stat[0], inv = stat[1];
    float4 g  = ((const float4*)gamma)[tid];
    float4 bt = ((const float4*)beta)[tid];
    float4 o4 = make_float4((x0 - mean) * inv * g.x + bt.x,
                            (x1 - mean) * inv * g.y + bt.y,
                            (x2 - mean) * inv * g.z + bt.z,
                            (x3 - mean) * inv * g.w + bt.w);
    ((float4*)(out + (size_t)row * 1024))[tid] = o4;
}

// ---------------------------------------------------------------------------
extern "C" void kernel_launch(void* const* d_in, const int* in_sizes, int n_in,
                              void* d_out, int out_size) {
    (void)in_sizes; (void)n_in; (void)out_size;
    const float* q     = (const float*)d_in[0];
    const float* v     = (const float*)d_in[2];
    const float* Wv    = (const float*)d_in[6];
    const float* Wo    = (const float*)d_in[7];
    const float* gamma = (const float*)d_in[8];
    const float* beta  = (const float*)d_in[9];
    float* out = (float*)d_out;

    float *part, *rowpart, *wosum, *outrows;
    cudaGetSymbolAddress((void**)&part,    g_part);
    cudaGetSymbolAddress((void**)&rowpart, g_rowpart);
    cudaGetSymbolAddress((void**)&wosum,   g_wosum);
    cudaGetSymbolAddress((void**)&outrows, g_outrows);

    prep_kernel   <<<320, 256>>>(v, Wo, part, wosum);
    vwv_kernel    <<<dim3(4, 8), 256>>>(part, Wv, rowpart);
    outrows_kernel<<<dim3(8, 8), 256>>>(rowpart, wosum, outrows);
    ln_kernel     <<<4096, 256>>>(outrows, q, gamma, beta, out);
}

// round 5
// speedup vs baseline: 1.1622x; 1.1047x over previous
#include <cuda_runtime.h>

// Scratch (device globals — no runtime allocation allowed)
__device__ float g_part   [4 * 64 * 1024];  // partial column sums of v (64 chunks of 16 rows)
__device__ float g_rowpart[8 * 4 * 1024];   // split-K partials of vsum @ Wv
__device__ float g_wosum  [64 * 1024];      // WoSum[d][m] = sum_j Wo[j*64+d][m]
__device__ float g_outrows[64 * 1024];      // 16 distinct out rows per batch

// ---------------------------------------------------------------------------
// L1 (fused): blocks 0..255 -> colsum of v; blocks 256..319 -> wosum of Wo.
// ---------------------------------------------------------------------------
__global__ __launch_bounds__(256) void prep_kernel(const float* __restrict__ v,
                                                   const float* __restrict__ Wo,
                                                   float* __restrict__ part,
                                                   float* __restrict__ wosum) {
    const int t = threadIdx.x;
    if (blockIdx.x < 256) {
        const int s = blockIdx.x >> 2, b = blockIdx.x & 3;
        const float4* p = (const float4*)(v + ((size_t)(b * 1024 + s * 16)) * 1024) + t;
        float4 a0 = make_float4(0.f, 0.f, 0.f, 0.f);
        float4 a1 = make_float4(0.f, 0.f, 0.f, 0.f);
#pragma unroll
        for (int i = 0; i < 16; i += 2) {
            float4 x = p[(size_t)i * 256];
            float4 y = p[(size_t)(i + 1) * 256];
            a0.x += x.x; a0.y += x.y; a0.z += x.z; a0.w += x.w;
            a1.x += y.x; a1.y += y.y; a1.z += y.z; a1.w += y.w;
        }
        float4 r = make_float4(a0.x + a1.x, a0.y + a1.y, a0.z + a1.z, a0.w + a1.w);
        ((float4*)(part + (size_t)(b * 64 + s) * 1024))[t] = r;
    } else {
        const int d = blockIdx.x - 256;      // 0..63
        const float4* src = (const float4*)(Wo + (size_t)d * 1024) + t;
        float4 a0 = make_float4(0.f, 0.f, 0.f, 0.f);
        float4 a1 = make_float4(0.f, 0.f, 0.f, 0.f);
        float4 a2 = make_float4(0.f, 0.f, 0.f, 0.f);
        float4 a3 = make_float4(0.f, 0.f, 0.f, 0.f);
#pragma unroll
        for (int j = 0; j < 16; j += 4) {
            float4 x0 = src[(size_t)(j + 0) * 64 * 256];
            float4 x1 = src[(size_t)(j + 1) * 64 * 256];
            float4 x2 = src[(size_t)(j + 2) * 64 * 256];
            float4 x3 = src[(size_t)(j + 3) * 64 * 256];
            a0.x += x0.x; a0.y += x0.y; a0.z += x0.z; a0.w += x0.w;
            a1.x += x1.x; a1.y += x1.y; a1.z += x1.z; a1.w += x1.w;
            a2.x += x2.x; a2.y += x2.y; a2.z += x2.z; a2.w += x2.w;
            a3.x += x3.x; a3.y += x3.y; a3.z += x3.z; a3.w += x3.w;
        }
        float4 r = make_float4(a0.x + a1.x + a2.x + a3.x,
                               a0.y + a1.y + a2.y + a3.y,
                               a0.z + a1.z + a2.z + a3.z,
                               a0.w + a1.w + a2.w + a3.w);
        ((float4*)(wosum + (size_t)d * 1024))[t] = r;
    }
}

// ---------------------------------------------------------------------------
// L2: split-K of rowsum[b][o] = sum_k vsum[b][k] * Wv[k][o].
// ---------------------------------------------------------------------------
__global__ __launch_bounds__(256) void vwv_kernel(const float* __restrict__ part,
                                                  const float* __restrict__ Wv,
                                                  float* __restrict__ rowpart) {
    __shared__ float vs[4][128];
    const int oc = blockIdx.x, kc = blockIdx.y, t = threadIdx.x;
    for (int idx = t; idx < 512; idx += 256) {
        int b = idx >> 7, kk = idx & 127;
        int k = kc * 128 + kk;
        float a0 = 0.f, a1 = 0.f;
#pragma unroll
        for (int s = 0; s < 64; s += 2) {
            a0 += part[(size_t)(b * 64 + s) * 1024 + k];
            a1 += part[(size_t)(b * 64 + s + 1) * 1024 + k];
        }
        vs[b][kk] = a0 + a1;
    }
    __syncthreads();
    const int o = oc * 256 + t;
    float a0 = 0.f, a1 = 0.f, a2 = 0.f, a3 = 0.f;
#pragma unroll 8
    for (int kk = 0; kk < 128; ++kk) {
        float w = Wv[(size_t)(kc * 128 + kk) * 1024 + o];
        a0 = fmaf(vs[0][kk], w, a0);
        a1 = fmaf(vs[1][kk], w, a1);
        a2 = fmaf(vs[2][kk], w, a2);
        a3 = fmaf(vs[3][kk], w, a3);
    }
    float* rp = rowpart + (size_t)kc * 4096;
    rp[0 * 1024 + o] = a0;
    rp[1 * 1024 + o] = a1;
    rp[2 * 1024 + o] = a2;
    rp[3 * 1024 + o] = a3;
}

// ---------------------------------------------------------------------------
// L3: outrows = rs @ wosum   ([64,64] @ [64,1024]) with smem staging.
// ---------------------------------------------------------------------------
__global__ __launch_bounds__(256) void outrows_kernel(const float* __restrict__ rowpart,
                                                      const float* __restrict__ wosum,
                                                      float* __restrict__ outrows) {
    __shared__ float4 ws[64][32];   // [d][m4] : 64 x 128 floats = 32 KB
    __shared__ float  rs[8][64];
    const int mc = blockIdx.x, bng = blockIdx.y, t = threadIdx.x;

#pragma unroll
    for (int it = 0; it < 8; ++it) {
        int idx = t + it * 256;            // 0..2047
        int d = idx >> 5, m4 = idx & 31;
        ws[d][m4] = *((const float4*)(wosum + (size_t)d * 1024 + mc * 128) + m4);
    }
#pragma unroll
    for (int it = 0; it < 2; ++it) {
        int idx = t + it * 256;            // 0..511
        int bnl = idx >> 6, d = idx & 63;
        int bn = bng * 8 + bnl;
        int b = bn >> 4, o = (bn & 15) * 64 + d;
        float a = 0.f;
#pragma unroll
        for (int kc = 0; kc < 8; ++kc)
            a += rowpart[(size_t)(kc * 4 + b) * 1024 + o];
        rs[bnl][d] = a;
    }
    __syncthreads();

    const int bnl = t >> 5, m4 = t & 31;   // warp = bnl -> rs broadcast
    float4 acc = make_float4(0.f, 0.f, 0.f, 0.f);
#pragma unroll
    for (int d = 0; d < 64; ++d) {
        float a = rs[bnl][d];
        float4 w = ws[d][m4];
        acc.x = fmaf(a, w.x, acc.x);
        acc.y = fmaf(a, w.y, acc.y);
        acc.z = fmaf(a, w.z, acc.z);
        acc.w = fmaf(a, w.w, acc.w);
    }
    const int bn = bng * 8 + bnl;
    *((float4*)(outrows + (size_t)bn * 1024 + mc * 128) + m4) = acc;
}

// ---------------------------------------------------------------------------
// L4: residual add + LayerNorm, WARP-PER-ROW.
// 8 rows/block, 512 blocks. Thread owns 8 float4 of the row (stride-32
// coalesced), 16 independent LDG.128 in flight, shuffle-only reduction.
// ---------------------------------------------------------------------------
__global__ __launch_bounds__(256) void ln_kernel(const float* __restrict__ outrows,
                                                 const float* __restrict__ q,
                                                 const float* __restrict__ gamma,
                                                 const float* __restrict__ beta,
                                                 float* __restrict__ out) {
    const int warp = threadIdx.x >> 5, lane = threadIdx.x & 31;
    const int row  = blockIdx.x * 8 + warp;            // 0..4095
    const int bn   = (row >> 10) * 16 + ((row & 1023) >> 6);

    const float4* yp = (const float4*)(outrows + (size_t)bn * 1024) + lane;
    const float4* rp = (const float4*)(q + (size_t)row * 1024) + lane;

    float4 x[8];
    float s = 0.f, sq = 0.f;
#pragma unroll
    for (int it = 0; it < 8; ++it) {
        float4 y = yp[it * 32];
        float4 r = rp[it * 32];
        float4 xv = make_float4(y.x + r.x, y.y + r.y, y.z + r.z, y.w + r.w);
        x[it] = xv;
        s  += xv.x + xv.y + xv.z + xv.w;
        sq += xv.x * xv.x + xv.y * xv.y + xv.z * xv.z + xv.w * xv.w;
    }
#pragma unroll
    for (int off = 16; off >= 1; off >>= 1) {
        s  += __shfl_xor_sync(0xffffffffu, s,  off);
        sq += __shfl_xor_sync(0xffffffffu, sq, off);
    }
    const float mean = s * (1.f / 1024.f);
    const float inv  = rsqrtf(sq * (1.f / 1024.f) - mean * mean + 1e-6f);

    const float4* gp = (const float4*)gamma + lane;
    const float4* bp = (const float4*)beta  + lane;
    float4* op = (float4*)(out + (size_t)row * 1024) + lane;
#pragma unroll
    for (int it = 0; it < 8; ++it) {
        float4 g  = gp[it * 32];
        float4 bt = bp[it * 32];
        float4 xv = x[it];
        op[it * 32] = make_float4((xv.x - mean) * inv * g.x + bt.x,
                                  (xv.y - mean) * inv * g.y + bt.y,
                                  (xv.z - mean) * inv * g.z + bt.z,
                                  (xv.w - mean) * inv * g.w + bt.w);
    }
}

// ---------------------------------------------------------------------------
extern "C" void kernel_launch(void* const* d_in, const int* in_sizes, int n_in,
                              void* d_out, int out_size) {
    (void)in_sizes; (void)n_in; (void)out_size;
    const float* q     = (const float*)d_in[0];
    const float* v     = (const float*)d_in[2];
    const float* Wv    = (const float*)d_in[6];
    const float* Wo    = (const float*)d_in[7];
    const float* gamma = (const float*)d_in[8];
    const float* beta  = (const float*)d_in[9];
    float* out = (float*)d_out;

    float *part, *rowpart, *wosum, *outrows;
    cudaGetSymbolAddress((void**)&part,    g_part);
    cudaGetSymbolAddress((void**)&rowpart, g_rowpart);
    cudaGetSymbolAddress((void**)&wosum,   g_wosum);
    cudaGetSymbolAddress((void**)&outrows, g_outrows);

    prep_kernel   <<<320, 256>>>(v, Wo, part, wosum);
    vwv_kernel    <<<dim3(4, 8), 256>>>(part, Wv, rowpart);
    outrows_kernel<<<dim3(8, 8), 256>>>(rowpart, wosum, outrows);
    ln_kernel     <<<512, 256>>>(outrows, q, gamma, beta, out);
}